// round 9
// baseline (speedup 1.0000x reference)
#include <cuda_runtime.h>
#include <cuda_bf16.h>
#include <cuda_fp16.h>
#include <math.h>
#include <stdint.h>

#define N_NODES 50000
#define N_EDGES 1600000
#define IN_FEATS 256
#define HF 128           // N_HEADS * OUT_FEATS
#define NEG_SLOPE 0.2f
#define SCAN_BLOCKS 49   // ceil(50000/1024)

// -------- device scratch --------
__device__ __half g_fth[(size_t)N_NODES * HF];  // projected features fp16
__device__ float g_el[N_NODES * 2];
__device__ float g_er[N_NODES * 2];
__device__ int   g_deg[N_NODES];                // zero at every call entry (invariant)
__device__ int   g_off[N_NODES + 1];
__device__ int   g_cursor[N_NODES];
__device__ int2  g_edge2[N_EDGES];              // (src,dst) sorted by dst
__device__ int4  g_pdata[N_EDGES];              // (src, p0, p1, pad) sorted by dst
__device__ int   g_scanflag[64];                // 0 at call entry (invariant)
__device__ int   g_scanagg[64];
__device__ int   g_scandone;                    // 0 at call entry (invariant)

// ===========================================================================
// helpers
// ===========================================================================
__device__ __forceinline__ uint32_t smem_u32(const void* p) {
    uint32_t a;
    asm("{ .reg .u64 t; cvta.to.shared.u64 t, %1; cvt.u32.u64 %0, t; }" : "=r"(a) : "l"(p));
    return a;
}
__device__ __forceinline__ void ldsm4(uint32_t* r, uint32_t addr) {
    asm volatile("ldmatrix.sync.aligned.m8n8.x4.shared.b16 {%0,%1,%2,%3}, [%4];"
                 : "=r"(r[0]), "=r"(r[1]), "=r"(r[2]), "=r"(r[3]) : "r"(addr));
}
__device__ __forceinline__ void mma16816(float* d, const uint32_t* a, const uint32_t* b) {
    asm volatile("mma.sync.aligned.m16n8k16.row.col.f32.bf16.bf16.f32 "
                 "{%0,%1,%2,%3}, {%4,%5,%6,%7}, {%8,%9}, {%0,%1,%2,%3};"
                 : "+f"(d[0]), "+f"(d[1]), "+f"(d[2]), "+f"(d[3])
                 : "r"(a[0]), "r"(a[1]), "r"(a[2]), "r"(a[3]), "r"(b[0]), "r"(b[1]));
}

// smem byte offsets (dynamic, 64 KB)
#define AHI 0
#define ALO 16384
#define BHI 32768
#define BLO 49152
#define SM_TOTAL 65536

// ===========================================================================
// Kernel 1: bf16-split mma.sync GEMM + fused attn logits + fp16 ft store
// ===========================================================================
__global__ void __launch_bounds__(256)
gemm_mma(const float* __restrict__ A, const float* __restrict__ W,
         const float* __restrict__ al, const float* __restrict__ ar_,
         __half* __restrict__ fth, float* __restrict__ el, float* __restrict__ er,
         int M) {
    extern __shared__ char smem[];
    const uint32_t sb = smem_u32(smem);
    const int tid = threadIdx.x;
    const int wid = tid >> 5;
    const int lane = tid & 31;
    const int warpRow = wid & 3;
    const int warpCol = wid >> 2;
    const int m0 = blockIdx.x * 128;

    float acc[2][8][4];
    #pragma unroll
    for (int a = 0; a < 2; a++)
        #pragma unroll
        for (int b = 0; b < 8; b++)
            #pragma unroll
            for (int c = 0; c < 4; c++) acc[a][b][c] = 0.f;

    for (int c = 0; c < 4; c++) {
        const int kc = c * 64;
        #pragma unroll
        for (int i = 0; i < 16; i++) {
            int idx = tid + i * 256;
            int row = idx >> 5, kp = idx & 31;
            int gr = m0 + row;
            float2 a = (gr < M) ? __ldcs((const float2*)(A + (size_t)gr * IN_FEATS + kc + kp * 2))
                                : make_float2(0.f, 0.f);
            __nv_bfloat16 hx = __float2bfloat16(a.x), hy = __float2bfloat16(a.y);
            float lx = a.x - __bfloat162float(hx), ly = a.y - __bfloat162float(hy);
            uint32_t off = row * 128 + ((kp * 4) ^ ((row & 7) << 4));
            *(__nv_bfloat162*)(smem + AHI + off) = __halves2bfloat162(hx, hy);
            *(__nv_bfloat162*)(smem + ALO + off) =
                __halves2bfloat162(__float2bfloat16(lx), __float2bfloat16(ly));
        }
        #pragma unroll
        for (int i = 0; i < 32; i++) {
            int idx = tid + i * 256;
            int kr = idx >> 7, n = idx & 127;
            float b = __ldg(W + (size_t)(kc + kr) * HF + n);
            __nv_bfloat16 h = __float2bfloat16(b);
            float l = b - __bfloat162float(h);
            uint32_t off = n * 128 + ((kr * 2) ^ ((n & 7) << 4));
            *(__nv_bfloat16*)(smem + BHI + off) = h;
            *(__nv_bfloat16*)(smem + BLO + off) = __float2bfloat16(l);
        }
        __syncthreads();

        #pragma unroll
        for (int ks = 0; ks < 4; ks++) {
            uint32_t ahi[2][4], alo[2][4], bh[8][2], bl[8][2];
            #pragma unroll
            for (int tm = 0; tm < 2; tm++) {
                int row = warpRow * 32 + tm * 16 + (lane & 15);
                int kb = ks * 32 + ((lane >> 4) << 4);
                uint32_t off = row * 128 + (kb ^ ((row & 7) << 4));
                ldsm4(ahi[tm], sb + AHI + off);
                ldsm4(alo[tm], sb + ALO + off);
            }
            #pragma unroll
            for (int tp = 0; tp < 4; tp++) {
                int n = warpCol * 64 + tp * 16 + ((lane >> 4) << 3) + (lane & 7);
                int kb = ks * 32 + (((lane >> 3) & 1) << 4);
                uint32_t off = n * 128 + (kb ^ ((n & 7) << 4));
                uint32_t r[4];
                ldsm4(r, sb + BHI + off);
                bh[tp * 2][0] = r[0]; bh[tp * 2][1] = r[1];
                bh[tp * 2 + 1][0] = r[2]; bh[tp * 2 + 1][1] = r[3];
                ldsm4(r, sb + BLO + off);
                bl[tp * 2][0] = r[0]; bl[tp * 2][1] = r[1];
                bl[tp * 2 + 1][0] = r[2]; bl[tp * 2 + 1][1] = r[3];
            }
            #pragma unroll
            for (int tm = 0; tm < 2; tm++)
                #pragma unroll
                for (int tn = 0; tn < 8; tn++) {
                    mma16816(acc[tm][tn], ahi[tm], bh[tn]);
                    mma16816(acc[tm][tn], ahi[tm], bl[tn]);
                    mma16816(acc[tm][tn], alo[tm], bh[tn]);
                }
        }
        __syncthreads();
    }

    const int qr = lane >> 2, qc = lane & 3;
    #pragma unroll
    for (int tm = 0; tm < 2; tm++) {
        #pragma unroll
        for (int h = 0; h < 2; h++) {
            int row = m0 + warpRow * 32 + tm * 16 + 8 * h + qr;
            float dotl = 0.f, dotr = 0.f;
            #pragma unroll
            for (int tn = 0; tn < 8; tn++) {
                float v0 = acc[tm][tn][2 * h + 0];
                float v1 = acc[tm][tn][2 * h + 1];
                int col = warpCol * 64 + tn * 8 + qc * 2;
                dotl = fmaf(v0, __ldg(al + col), fmaf(v1, __ldg(al + col + 1), dotl));
                dotr = fmaf(v0, __ldg(ar_ + col), fmaf(v1, __ldg(ar_ + col + 1), dotr));
                if (row < M)
                    *(__half2*)(fth + (size_t)row * HF + col) = __floats2half2_rn(v0, v1);
            }
            dotl += __shfl_xor_sync(0xffffffffu, dotl, 1);
            dotl += __shfl_xor_sync(0xffffffffu, dotl, 2);
            dotr += __shfl_xor_sync(0xffffffffu, dotr, 1);
            dotr += __shfl_xor_sync(0xffffffffu, dotr, 2);
            if (qc == 0 && row < M) {
                el[row * 2 + warpCol] = dotl;
                er[row * 2 + warpCol] = dotr;
            }
        }
    }
}

// ===========================================================================
// CSR build
// ===========================================================================
__global__ void __launch_bounds__(256)
hist_dst(const int4* __restrict__ dst4) {
    int stride = gridDim.x * blockDim.x;
    for (int i = blockIdx.x * blockDim.x + threadIdx.x; i < N_EDGES / 4; i += stride) {
        int4 d = __ldcs(dst4 + i);
        atomicAdd(&g_deg[d.x], 1);
        atomicAdd(&g_deg[d.y], 1);
        atomicAdd(&g_deg[d.z], 1);
        atomicAdd(&g_deg[d.w], 1);
    }
}

__device__ __forceinline__ int warp_incl_scan(int v, int lane) {
    #pragma unroll
    for (int d = 1; d < 32; d <<= 1) {
        int t = __shfl_up_sync(0xffffffffu, v, d);
        if (lane >= d) v += t;
    }
    return v;
}

// Single-pass scan with decoupled lookback; zeroes g_deg + resets its flags.
__global__ void scan_fused() {
    __shared__ int ws[32];
    __shared__ int sprefix;
    int tid = threadIdx.x;
    int lane = tid & 31, wid = tid >> 5;
    int b = blockIdx.x;
    int i = b * 1024 + tid;
    int v = (i < N_NODES) ? g_deg[i] : 0;
    int incl = warp_incl_scan(v, lane);
    if (lane == 31) ws[wid] = incl;
    __syncthreads();
    if (wid == 0) ws[lane] = warp_incl_scan(ws[lane], lane);
    __syncthreads();
    int local = incl + (wid > 0 ? ws[wid - 1] : 0);
    int btotal = ws[31];

    if (wid == 0) {
        if (lane == 0) {
            g_scanagg[b] = btotal;
            __threadfence();
            atomicExch(&g_scanflag[b], 1);
        }
        int pref = 0;
        for (int p = lane; p < b; p += 32) {
            while (atomicAdd(&g_scanflag[p], 0) == 0) {}
            pref += atomicAdd(&g_scanagg[p], 0);
        }
        #pragma unroll
        for (int d = 16; d; d >>= 1) pref += __shfl_xor_sync(0xffffffffu, pref, d);
        if (lane == 0) {
            sprefix = pref;
            __threadfence();
            int d = atomicAdd(&g_scandone, 1);
            if (d == SCAN_BLOCKS - 1) {
                for (int p = 0; p < SCAN_BLOCKS; p++) g_scanflag[p] = 0;
                g_scandone = 0;
            }
        }
    }
    __syncthreads();
    int ginc = local + sprefix;
    if (i < N_NODES) {
        g_off[i + 1] = ginc;
        g_cursor[i] = ginc - v;
        g_deg[i] = 0;                              // restore invariant
    }
    if (b == 0 && tid == 0) g_off[0] = 0;
}

__global__ void __launch_bounds__(256)
scatter_edges(const int4* __restrict__ src4, const int4* __restrict__ dst4) {
    int stride = gridDim.x * blockDim.x;
    for (int i = blockIdx.x * blockDim.x + threadIdx.x; i < N_EDGES / 4; i += stride) {
        int4 s = __ldcs(src4 + i);
        int4 d = __ldcs(dst4 + i);
        int p;
        p = atomicAdd(&g_cursor[d.x], 1); g_edge2[p] = make_int2(s.x, d.x);
        p = atomicAdd(&g_cursor[d.y], 1); g_edge2[p] = make_int2(s.y, d.y);
        p = atomicAdd(&g_cursor[d.z], 1); g_edge2[p] = make_int2(s.z, d.z);
        p = atomicAdd(&g_cursor[d.w], 1); g_edge2[p] = make_int2(s.w, d.w);
    }
}

// ===========================================================================
// edge_p: per-edge softmax numerators (fp32), written in dst-sorted order.
// pdata[i] = {src, bits(p0), bits(p1), 0}
// ===========================================================================
__global__ void __launch_bounds__(256)
edge_p() {
    int i = blockIdx.x * blockDim.x + threadIdx.x;
    if (i >= N_EDGES) return;
    int2 e = __ldcs(&g_edge2[i]);
    float2 elv = *(const float2*)(g_el + 2 * e.x);
    float2 erv = *(const float2*)(g_er + 2 * e.y);
    float e0 = elv.x + erv.x; e0 = fmaxf(e0, NEG_SLOPE * e0);
    float e1 = elv.y + erv.y; e1 = fmaxf(e1, NEG_SLOPE * e1);
    int4 o;
    o.x = e.x;
    o.y = __float_as_int(__expf(e0));
    o.z = __float_as_int(__expf(e1));
    o.w = 0;
    __stcs(&g_pdata[i], o);
}

// ===========================================================================
// warp-per-node aggregation: broadcast int4 loads, no shuffles, no reduce.
// ===========================================================================
__global__ void gat_agg(float* __restrict__ out) {
    int gtid = blockIdx.x * blockDim.x + threadIdx.x;
    int node = gtid >> 5;
    int lane = gtid & 31;
    if (node >= N_NODES) return;

    const int beg = g_off[node];
    const int end = g_off[node + 1];
    const int head1 = lane >> 4;

    const uint2* ftp = (const uint2*)g_fth;
    float4 acc = make_float4(0.f, 0.f, 0.f, 0.f);
    float s0 = 0.f, s1 = 0.f;

    #pragma unroll 4
    for (int i = beg; i < end; i++) {
        int4 pd = __ldcs(&g_pdata[i]);            // broadcast: 1 wavefront
        float p0 = __int_as_float(pd.y);
        float p1 = __int_as_float(pd.z);
        s0 += p0; s1 += p1;
        float pp = head1 ? p1 : p0;
        uint2 v = ftp[(size_t)pd.x * 32 + lane];  // gather ft row (L2-resident)
        float2 f0 = __half22float2(*(__half2*)&v.x);
        float2 f1 = __half22float2(*(__half2*)&v.y);
        acc.x = fmaf(pp, f0.x, acc.x);
        acc.y = fmaf(pp, f0.y, acc.y);
        acc.z = fmaf(pp, f1.x, acc.z);
        acc.w = fmaf(pp, f1.y, acc.w);
    }

    float inv = 1.f / fmaxf(head1 ? s1 : s0, 1e-20f);
    float4 o = make_float4(acc.x * inv, acc.y * inv, acc.z * inv, acc.w * inv);
    __stcs(((float4*)out) + (size_t)node * 32 + lane, o);
}

// ===========================================================================
extern "C" void kernel_launch(void* const* d_in, const int* in_sizes, int n_in,
                              void* d_out, int out_size) {
    const float* feat   = (const float*)d_in[0];
    const int*   src    = (const int*)  d_in[1];
    const int*   dst    = (const int*)  d_in[2];
    const float* W      = (const float*)d_in[3];
    const float* attn_l = (const float*)d_in[4];
    const float* attn_r = (const float*)d_in[5];
    float* out = (float*)d_out;

    __half* fth_p; cudaGetSymbolAddress((void**)&fth_p, g_fth);
    float*  el_p;  cudaGetSymbolAddress((void**)&el_p, g_el);
    float*  er_p;  cudaGetSymbolAddress((void**)&er_p, g_er);

    cudaFuncSetAttribute(gemm_mma, cudaFuncAttributeMaxDynamicSharedMemorySize, SM_TOTAL);

    static cudaStream_t s1 = [] {
        cudaStream_t s; cudaStreamCreateWithFlags(&s, cudaStreamNonBlocking); return s;
    }();
    static cudaEvent_t e0 = [] {
        cudaEvent_t e; cudaEventCreateWithFlags(&e, cudaEventDisableTiming); return e;
    }();
    static cudaEvent_t e1 = [] {
        cudaEvent_t e; cudaEventCreateWithFlags(&e, cudaEventDisableTiming); return e;
    }();

    // Fork: GEMM on s1 (independent of CSR build).
    cudaEventRecord(e0, 0);
    cudaStreamWaitEvent(s1, e0, 0);
    gemm_mma<<<(N_NODES + 127) / 128, 256, SM_TOTAL, s1>>>(feat, W, attn_l, attn_r,
                                                           fth_p, el_p, er_p, N_NODES);
    cudaEventRecord(e1, s1);

    // Main stream: CSR chain (g_deg zero on entry by invariant).
    hist_dst<<<448, 256>>>((const int4*)dst);
    scan_fused<<<SCAN_BLOCKS, 1024>>>();
    scatter_edges<<<448, 256>>>((const int4*)src, (const int4*)dst);

    // Join GEMM, then per-edge coefficients, then aggregate.
    cudaStreamWaitEvent(0, e1, 0);
    edge_p<<<(N_EDGES + 255) / 256, 256>>>();
    gat_agg<<<(N_NODES * 32 + 255) / 256, 256>>>(out);
}

// round 10
// speedup vs baseline: 1.1286x; 1.1286x over previous
#include <cuda_runtime.h>
#include <cuda_bf16.h>
#include <cuda_fp16.h>
#include <math.h>
#include <stdint.h>

#define N_NODES 50000
#define N_EDGES 1600000
#define IN_FEATS 256
#define HF 128           // N_HEADS * OUT_FEATS
#define NEG_SLOPE 0.2f
#define SCAN_BLOCKS 49   // ceil(50000/1024)

// -------- device scratch --------
__device__ __half g_fth[(size_t)N_NODES * HF];  // projected features fp16
__device__ float g_el[N_NODES * 2];
__device__ float g_er[N_NODES * 2];
__device__ int   g_deg[N_NODES];                // zero at every call entry (invariant)
__device__ int   g_off[N_NODES + 1];
__device__ int   g_cursor[N_NODES];
__device__ int   g_ssrc[N_EDGES];               // src ids sorted by dst
__device__ int   g_scanflag[64];                // 0 at call entry (invariant)
__device__ int   g_scanagg[64];
__device__ int   g_scandone;                    // 0 at call entry (invariant)

// ===========================================================================
// helpers
// ===========================================================================
__device__ __forceinline__ uint32_t smem_u32(const void* p) {
    uint32_t a;
    asm("{ .reg .u64 t; cvta.to.shared.u64 t, %1; cvt.u32.u64 %0, t; }" : "=r"(a) : "l"(p));
    return a;
}
__device__ __forceinline__ void ldsm4(uint32_t* r, uint32_t addr) {
    asm volatile("ldmatrix.sync.aligned.m8n8.x4.shared.b16 {%0,%1,%2,%3}, [%4];"
                 : "=r"(r[0]), "=r"(r[1]), "=r"(r[2]), "=r"(r[3]) : "r"(addr));
}
__device__ __forceinline__ void mma16816(float* d, const uint32_t* a, const uint32_t* b) {
    asm volatile("mma.sync.aligned.m16n8k16.row.col.f32.bf16.bf16.f32 "
                 "{%0,%1,%2,%3}, {%4,%5,%6,%7}, {%8,%9}, {%0,%1,%2,%3};"
                 : "+f"(d[0]), "+f"(d[1]), "+f"(d[2]), "+f"(d[3])
                 : "r"(a[0]), "r"(a[1]), "r"(a[2]), "r"(a[3]), "r"(b[0]), "r"(b[1]));
}

// smem byte offsets (dynamic, 64 KB)
#define AHI 0
#define ALO 16384
#define BHI 32768
#define BLO 49152
#define SM_TOTAL 65536

// ===========================================================================
// Kernel 1: bf16-split mma.sync GEMM + fused attn logits + fp16 ft store
// ===========================================================================
__global__ void __launch_bounds__(256)
gemm_mma(const float* __restrict__ A, const float* __restrict__ W,
         const float* __restrict__ al, const float* __restrict__ ar_,
         __half* __restrict__ fth, float* __restrict__ el, float* __restrict__ er,
         int M) {
    extern __shared__ char smem[];
    const uint32_t sb = smem_u32(smem);
    const int tid = threadIdx.x;
    const int wid = tid >> 5;
    const int lane = tid & 31;
    const int warpRow = wid & 3;
    const int warpCol = wid >> 2;
    const int m0 = blockIdx.x * 128;

    float acc[2][8][4];
    #pragma unroll
    for (int a = 0; a < 2; a++)
        #pragma unroll
        for (int b = 0; b < 8; b++)
            #pragma unroll
            for (int c = 0; c < 4; c++) acc[a][b][c] = 0.f;

    for (int c = 0; c < 4; c++) {
        const int kc = c * 64;
        #pragma unroll
        for (int i = 0; i < 16; i++) {
            int idx = tid + i * 256;
            int row = idx >> 5, kp = idx & 31;
            int gr = m0 + row;
            float2 a = (gr < M) ? __ldcs((const float2*)(A + (size_t)gr * IN_FEATS + kc + kp * 2))
                                : make_float2(0.f, 0.f);
            __nv_bfloat16 hx = __float2bfloat16(a.x), hy = __float2bfloat16(a.y);
            float lx = a.x - __bfloat162float(hx), ly = a.y - __bfloat162float(hy);
            uint32_t off = row * 128 + ((kp * 4) ^ ((row & 7) << 4));
            *(__nv_bfloat162*)(smem + AHI + off) = __halves2bfloat162(hx, hy);
            *(__nv_bfloat162*)(smem + ALO + off) =
                __halves2bfloat162(__float2bfloat16(lx), __float2bfloat16(ly));
        }
        #pragma unroll
        for (int i = 0; i < 32; i++) {
            int idx = tid + i * 256;
            int kr = idx >> 7, n = idx & 127;
            float b = __ldg(W + (size_t)(kc + kr) * HF + n);
            __nv_bfloat16 h = __float2bfloat16(b);
            float l = b - __bfloat162float(h);
            uint32_t off = n * 128 + ((kr * 2) ^ ((n & 7) << 4));
            *(__nv_bfloat16*)(smem + BHI + off) = h;
            *(__nv_bfloat16*)(smem + BLO + off) = __float2bfloat16(l);
        }
        __syncthreads();

        #pragma unroll
        for (int ks = 0; ks < 4; ks++) {
            uint32_t ahi[2][4], alo[2][4], bh[8][2], bl[8][2];
            #pragma unroll
            for (int tm = 0; tm < 2; tm++) {
                int row = warpRow * 32 + tm * 16 + (lane & 15);
                int kb = ks * 32 + ((lane >> 4) << 4);
                uint32_t off = row * 128 + (kb ^ ((row & 7) << 4));
                ldsm4(ahi[tm], sb + AHI + off);
                ldsm4(alo[tm], sb + ALO + off);
            }
            #pragma unroll
            for (int tp = 0; tp < 4; tp++) {
                int n = warpCol * 64 + tp * 16 + ((lane >> 4) << 3) + (lane & 7);
                int kb = ks * 32 + (((lane >> 3) & 1) << 4);
                uint32_t off = n * 128 + (kb ^ ((n & 7) << 4));
                uint32_t r[4];
                ldsm4(r, sb + BHI + off);
                bh[tp * 2][0] = r[0]; bh[tp * 2][1] = r[1];
                bh[tp * 2 + 1][0] = r[2]; bh[tp * 2 + 1][1] = r[3];
                ldsm4(r, sb + BLO + off);
                bl[tp * 2][0] = r[0]; bl[tp * 2][1] = r[1];
                bl[tp * 2 + 1][0] = r[2]; bl[tp * 2 + 1][1] = r[3];
            }
            #pragma unroll
            for (int tm = 0; tm < 2; tm++)
                #pragma unroll
                for (int tn = 0; tn < 8; tn++) {
                    mma16816(acc[tm][tn], ahi[tm], bh[tn]);
                    mma16816(acc[tm][tn], ahi[tm], bl[tn]);
                    mma16816(acc[tm][tn], alo[tm], bh[tn]);
                }
        }
        __syncthreads();
    }

    const int qr = lane >> 2, qc = lane & 3;
    #pragma unroll
    for (int tm = 0; tm < 2; tm++) {
        #pragma unroll
        for (int h = 0; h < 2; h++) {
            int row = m0 + warpRow * 32 + tm * 16 + 8 * h + qr;
            float dotl = 0.f, dotr = 0.f;
            #pragma unroll
            for (int tn = 0; tn < 8; tn++) {
                float v0 = acc[tm][tn][2 * h + 0];
                float v1 = acc[tm][tn][2 * h + 1];
                int col = warpCol * 64 + tn * 8 + qc * 2;
                dotl = fmaf(v0, __ldg(al + col), fmaf(v1, __ldg(al + col + 1), dotl));
                dotr = fmaf(v0, __ldg(ar_ + col), fmaf(v1, __ldg(ar_ + col + 1), dotr));
                if (row < M)
                    *(__half2*)(fth + (size_t)row * HF + col) = __floats2half2_rn(v0, v1);
            }
            dotl += __shfl_xor_sync(0xffffffffu, dotl, 1);
            dotl += __shfl_xor_sync(0xffffffffu, dotl, 2);
            dotr += __shfl_xor_sync(0xffffffffu, dotr, 1);
            dotr += __shfl_xor_sync(0xffffffffu, dotr, 2);
            if (qc == 0 && row < M) {
                el[row * 2 + warpCol] = dotl;
                er[row * 2 + warpCol] = dotr;
            }
        }
    }
}

// ===========================================================================
// CSR build
// ===========================================================================
__global__ void __launch_bounds__(256)
hist_dst(const int4* __restrict__ dst4) {
    int stride = gridDim.x * blockDim.x;
    for (int i = blockIdx.x * blockDim.x + threadIdx.x; i < N_EDGES / 4; i += stride) {
        int4 d = __ldcs(dst4 + i);
        atomicAdd(&g_deg[d.x], 1);
        atomicAdd(&g_deg[d.y], 1);
        atomicAdd(&g_deg[d.z], 1);
        atomicAdd(&g_deg[d.w], 1);
    }
}

__device__ __forceinline__ int warp_incl_scan(int v, int lane) {
    #pragma unroll
    for (int d = 1; d < 32; d <<= 1) {
        int t = __shfl_up_sync(0xffffffffu, v, d);
        if (lane >= d) v += t;
    }
    return v;
}

// Single-pass scan with decoupled lookback; zeroes g_deg + resets its flags.
__global__ void scan_fused() {
    __shared__ int ws[32];
    __shared__ int sprefix;
    int tid = threadIdx.x;
    int lane = tid & 31, wid = tid >> 5;
    int b = blockIdx.x;
    int i = b * 1024 + tid;
    int v = (i < N_NODES) ? g_deg[i] : 0;
    int incl = warp_incl_scan(v, lane);
    if (lane == 31) ws[wid] = incl;
    __syncthreads();
    if (wid == 0) ws[lane] = warp_incl_scan(ws[lane], lane);
    __syncthreads();
    int local = incl + (wid > 0 ? ws[wid - 1] : 0);
    int btotal = ws[31];

    if (wid == 0) {
        if (lane == 0) {
            g_scanagg[b] = btotal;
            __threadfence();
            atomicExch(&g_scanflag[b], 1);
        }
        int pref = 0;
        for (int p = lane; p < b; p += 32) {
            while (atomicAdd(&g_scanflag[p], 0) == 0) {}
            pref += atomicAdd(&g_scanagg[p], 0);
        }
        #pragma unroll
        for (int d = 16; d; d >>= 1) pref += __shfl_xor_sync(0xffffffffu, pref, d);
        if (lane == 0) {
            sprefix = pref;
            __threadfence();
            int d = atomicAdd(&g_scandone, 1);
            if (d == SCAN_BLOCKS - 1) {
                for (int p = 0; p < SCAN_BLOCKS; p++) g_scanflag[p] = 0;
                g_scandone = 0;
            }
        }
    }
    __syncthreads();
    int ginc = local + sprefix;
    if (i < N_NODES) {
        g_off[i + 1] = ginc;
        g_cursor[i] = ginc - v;
        g_deg[i] = 0;                              // restore invariant
    }
    if (b == 0 && tid == 0) g_off[0] = 0;
}

__global__ void __launch_bounds__(256)
scatter_edges(const int4* __restrict__ src4, const int4* __restrict__ dst4) {
    int stride = gridDim.x * blockDim.x;
    for (int i = blockIdx.x * blockDim.x + threadIdx.x; i < N_EDGES / 4; i += stride) {
        int4 s = __ldcs(src4 + i);
        int4 d = __ldcs(dst4 + i);
        int p;
        p = atomicAdd(&g_cursor[d.x], 1); g_ssrc[p] = s.x;
        p = atomicAdd(&g_cursor[d.y], 1); g_ssrc[p] = s.y;
        p = atomicAdd(&g_cursor[d.z], 1); g_ssrc[p] = s.z;
        p = atomicAdd(&g_cursor[d.w], 1); g_ssrc[p] = s.w;
    }
}

// ===========================================================================
// warp-per-node softmax + aggregation: 2 edges/iter, half-warp per edge,
// uint4 (8-half) ft loads. Lanes 0-15 edge e, lanes 16-31 edge e+1.
// Each lane owns 8 feature positions (l16*8 .. l16*8+7); head = l16>>3.
// ===========================================================================
__global__ void gat_agg(float* __restrict__ out) {
    int gtid = blockIdx.x * blockDim.x + threadIdx.x;
    int node = gtid >> 5;
    int lane = gtid & 31;
    if (node >= N_NODES) return;

    const int beg = g_off[node];
    const int end = g_off[node + 1];
    const float er0 = g_er[node * 2 + 0];
    const float er1 = g_er[node * 2 + 1];
    const int half16 = lane >> 4;    // which edge of the pair
    const int l16 = lane & 15;       // feature-chunk owner
    const int head = l16 >> 3;       // 0: feats [0,64), 1: feats [64,128)

    const uint4* ftp = (const uint4*)g_fth;   // 16 uint4 per row
    float acc[8];
    #pragma unroll
    for (int j = 0; j < 8; j++) acc[j] = 0.f;
    float s0 = 0.f, s1 = 0.f;

    for (int cb = beg; cb < end; cb += 32) {
        int i = cb + lane;
        float p0 = 0.f, p1 = 0.f;
        int sv = 0;
        if (i < end) {
            sv = __ldcs(g_ssrc + i);
            float2 elv = *(const float2*)(g_el + 2 * sv);
            float e0 = elv.x + er0; e0 = fmaxf(e0, NEG_SLOPE * e0);
            float e1 = elv.y + er1; e1 = fmaxf(e1, NEG_SLOPE * e1);
            p0 = __expf(e0);
            p1 = __expf(e1);
        }
        s0 += p0; s1 += p1;
        int cnt = min(32, end - cb);
        #pragma unroll 2
        for (int e = 0; e < cnt; e += 2) {
            int eA = e + half16;                   // this half-warp's edge
            bool valid = eA < cnt;
            int esel = valid ? eA : 0;
            int   ss  = __shfl_sync(0xffffffffu, sv, esel);
            float pp0 = __shfl_sync(0xffffffffu, p0, esel);
            float pp1 = __shfl_sync(0xffffffffu, p1, esel);
            float pp = head ? pp1 : pp0;
            if (!valid) pp = 0.f;
            uint4 v = ftp[(size_t)ss * 16 + l16];  // 8 halves
            float2 f0 = __half22float2(*(__half2*)&v.x);
            float2 f1 = __half22float2(*(__half2*)&v.y);
            float2 f2 = __half22float2(*(__half2*)&v.z);
            float2 f3 = __half22float2(*(__half2*)&v.w);
            acc[0] = fmaf(pp, f0.x, acc[0]);
            acc[1] = fmaf(pp, f0.y, acc[1]);
            acc[2] = fmaf(pp, f1.x, acc[2]);
            acc[3] = fmaf(pp, f1.y, acc[3]);
            acc[4] = fmaf(pp, f2.x, acc[4]);
            acc[5] = fmaf(pp, f2.y, acc[5]);
            acc[6] = fmaf(pp, f3.x, acc[6]);
            acc[7] = fmaf(pp, f3.y, acc[7]);
        }
    }

    // combine the two half-warps' accumulators (same feature positions)
    #pragma unroll
    for (int j = 0; j < 8; j++)
        acc[j] += __shfl_xor_sync(0xffffffffu, acc[j], 16);

    // reduce denominators across the warp
    #pragma unroll
    for (int d = 16; d; d >>= 1) {
        s0 += __shfl_xor_sync(0xffffffffu, s0, d);
        s1 += __shfl_xor_sync(0xffffffffu, s1, d);
    }
    float inv = 1.f / fmaxf(head ? s1 : s0, 1e-20f);

    if (half16 == 0) {
        float4* op = (float4*)(out + (size_t)node * HF + l16 * 8);
        __stcs(op,     make_float4(acc[0] * inv, acc[1] * inv, acc[2] * inv, acc[3] * inv));
        __stcs(op + 1, make_float4(acc[4] * inv, acc[5] * inv, acc[6] * inv, acc[7] * inv));
    }
}

// ===========================================================================
extern "C" void kernel_launch(void* const* d_in, const int* in_sizes, int n_in,
                              void* d_out, int out_size) {
    const float* feat   = (const float*)d_in[0];
    const int*   src    = (const int*)  d_in[1];
    const int*   dst    = (const int*)  d_in[2];
    const float* W      = (const float*)d_in[3];
    const float* attn_l = (const float*)d_in[4];
    const float* attn_r = (const float*)d_in[5];
    float* out = (float*)d_out;

    __half* fth_p; cudaGetSymbolAddress((void**)&fth_p, g_fth);
    float*  el_p;  cudaGetSymbolAddress((void**)&el_p, g_el);
    float*  er_p;  cudaGetSymbolAddress((void**)&er_p, g_er);

    cudaFuncSetAttribute(gemm_mma, cudaFuncAttributeMaxDynamicSharedMemorySize, SM_TOTAL);

    static cudaStream_t s1 = [] {
        cudaStream_t s; cudaStreamCreateWithFlags(&s, cudaStreamNonBlocking); return s;
    }();
    static cudaEvent_t e0 = [] {
        cudaEvent_t e; cudaEventCreateWithFlags(&e, cudaEventDisableTiming); return e;
    }();
    static cudaEvent_t e1 = [] {
        cudaEvent_t e; cudaEventCreateWithFlags(&e, cudaEventDisableTiming); return e;
    }();

    // Fork: GEMM on s1 (independent of CSR build).
    cudaEventRecord(e0, 0);
    cudaStreamWaitEvent(s1, e0, 0);
    gemm_mma<<<(N_NODES + 127) / 128, 256, SM_TOTAL, s1>>>(feat, W, attn_l, attn_r,
                                                           fth_p, el_p, er_p, N_NODES);
    cudaEventRecord(e1, s1);

    // Main stream: CSR chain (g_deg zero on entry by invariant).
    hist_dst<<<448, 256>>>((const int4*)dst);
    scan_fused<<<SCAN_BLOCKS, 1024>>>();
    scatter_edges<<<448, 256>>>((const int4*)src, (const int4*)dst);

    // Join, then aggregate.
    cudaStreamWaitEvent(0, e1, 0);
    gat_agg<<<(N_NODES * 32 + 255) / 256, 256>>>(out);
}

// round 11
// speedup vs baseline: 1.2000x; 1.0632x over previous
#include <cuda_runtime.h>
#include <cuda_bf16.h>
#include <cuda_fp16.h>
#include <math.h>
#include <stdint.h>

#define N_NODES 50000
#define N_EDGES 1600000
#define IN_FEATS 256
#define HF 128           // N_HEADS * OUT_FEATS
#define NEG_SLOPE 0.2f
#define SCAN_BLOCKS 49   // ceil(50000/1024)

// -------- device scratch --------
__device__ __half g_fth[(size_t)N_NODES * HF];  // projected features fp16
__device__ float g_el[N_NODES * 2];
__device__ float g_er[N_NODES * 2];
__device__ int   g_deg[N_NODES];                // zero at every call entry (invariant)
__device__ int   g_off[N_NODES + 1];
__device__ int   g_rank[N_EDGES];               // per-edge rank within dst bucket
__device__ int   g_ssrc[N_EDGES];               // src ids sorted by dst
__device__ int   g_scanflag[64];                // 0 at call entry (invariant)
__device__ int   g_scanagg[64];
__device__ int   g_scandone;                    // 0 at call entry (invariant)

// ===========================================================================
// helpers
// ===========================================================================
__device__ __forceinline__ uint32_t smem_u32(const void* p) {
    uint32_t a;
    asm("{ .reg .u64 t; cvta.to.shared.u64 t, %1; cvt.u32.u64 %0, t; }" : "=r"(a) : "l"(p));
    return a;
}
__device__ __forceinline__ void ldsm4(uint32_t* r, uint32_t addr) {
    asm volatile("ldmatrix.sync.aligned.m8n8.x4.shared.b16 {%0,%1,%2,%3}, [%4];"
                 : "=r"(r[0]), "=r"(r[1]), "=r"(r[2]), "=r"(r[3]) : "r"(addr));
}
__device__ __forceinline__ void mma16816(float* d, const uint32_t* a, const uint32_t* b) {
    asm volatile("mma.sync.aligned.m16n8k16.row.col.f32.bf16.bf16.f32 "
                 "{%0,%1,%2,%3}, {%4,%5,%6,%7}, {%8,%9}, {%0,%1,%2,%3};"
                 : "+f"(d[0]), "+f"(d[1]), "+f"(d[2]), "+f"(d[3])
                 : "r"(a[0]), "r"(a[1]), "r"(a[2]), "r"(a[3]), "r"(b[0]), "r"(b[1]));
}

// smem byte offsets (dynamic, 64 KB)
#define AHI 0
#define ALO 16384
#define BHI 32768
#define BLO 49152
#define SM_TOTAL 65536

// ===========================================================================
// Kernel 1: bf16-split mma.sync GEMM + fused attn logits + fp16 ft store
// ===========================================================================
__global__ void __launch_bounds__(256)
gemm_mma(const float* __restrict__ A, const float* __restrict__ W,
         const float* __restrict__ al, const float* __restrict__ ar_,
         __half* __restrict__ fth, float* __restrict__ el, float* __restrict__ er,
         int M) {
    extern __shared__ char smem[];
    const uint32_t sb = smem_u32(smem);
    const int tid = threadIdx.x;
    const int wid = tid >> 5;
    const int lane = tid & 31;
    const int warpRow = wid & 3;
    const int warpCol = wid >> 2;
    const int m0 = blockIdx.x * 128;

    float acc[2][8][4];
    #pragma unroll
    for (int a = 0; a < 2; a++)
        #pragma unroll
        for (int b = 0; b < 8; b++)
            #pragma unroll
            for (int c = 0; c < 4; c++) acc[a][b][c] = 0.f;

    for (int c = 0; c < 4; c++) {
        const int kc = c * 64;
        #pragma unroll
        for (int i = 0; i < 16; i++) {
            int idx = tid + i * 256;
            int row = idx >> 5, kp = idx & 31;
            int gr = m0 + row;
            float2 a = (gr < M) ? __ldcs((const float2*)(A + (size_t)gr * IN_FEATS + kc + kp * 2))
                                : make_float2(0.f, 0.f);
            __nv_bfloat16 hx = __float2bfloat16(a.x), hy = __float2bfloat16(a.y);
            float lx = a.x - __bfloat162float(hx), ly = a.y - __bfloat162float(hy);
            uint32_t off = row * 128 + ((kp * 4) ^ ((row & 7) << 4));
            *(__nv_bfloat162*)(smem + AHI + off) = __halves2bfloat162(hx, hy);
            *(__nv_bfloat162*)(smem + ALO + off) =
                __halves2bfloat162(__float2bfloat16(lx), __float2bfloat16(ly));
        }
        #pragma unroll
        for (int i = 0; i < 32; i++) {
            int idx = tid + i * 256;
            int kr = idx >> 7, n = idx & 127;
            float b = __ldg(W + (size_t)(kc + kr) * HF + n);
            __nv_bfloat16 h = __float2bfloat16(b);
            float l = b - __bfloat162float(h);
            uint32_t off = n * 128 + ((kr * 2) ^ ((n & 7) << 4));
            *(__nv_bfloat16*)(smem + BHI + off) = h;
            *(__nv_bfloat16*)(smem + BLO + off) = __float2bfloat16(l);
        }
        __syncthreads();

        #pragma unroll
        for (int ks = 0; ks < 4; ks++) {
            uint32_t ahi[2][4], alo[2][4], bh[8][2], bl[8][2];
            #pragma unroll
            for (int tm = 0; tm < 2; tm++) {
                int row = warpRow * 32 + tm * 16 + (lane & 15);
                int kb = ks * 32 + ((lane >> 4) << 4);
                uint32_t off = row * 128 + (kb ^ ((row & 7) << 4));
                ldsm4(ahi[tm], sb + AHI + off);
                ldsm4(alo[tm], sb + ALO + off);
            }
            #pragma unroll
            for (int tp = 0; tp < 4; tp++) {
                int n = warpCol * 64 + tp * 16 + ((lane >> 4) << 3) + (lane & 7);
                int kb = ks * 32 + (((lane >> 3) & 1) << 4);
                uint32_t off = n * 128 + (kb ^ ((n & 7) << 4));
                uint32_t r[4];
                ldsm4(r, sb + BHI + off);
                bh[tp * 2][0] = r[0]; bh[tp * 2][1] = r[1];
                bh[tp * 2 + 1][0] = r[2]; bh[tp * 2 + 1][1] = r[3];
                ldsm4(r, sb + BLO + off);
                bl[tp * 2][0] = r[0]; bl[tp * 2][1] = r[1];
                bl[tp * 2 + 1][0] = r[2]; bl[tp * 2 + 1][1] = r[3];
            }
            #pragma unroll
            for (int tm = 0; tm < 2; tm++)
                #pragma unroll
                for (int tn = 0; tn < 8; tn++) {
                    mma16816(acc[tm][tn], ahi[tm], bh[tn]);
                    mma16816(acc[tm][tn], ahi[tm], bl[tn]);
                    mma16816(acc[tm][tn], alo[tm], bh[tn]);
                }
        }
        __syncthreads();
    }

    const int qr = lane >> 2, qc = lane & 3;
    #pragma unroll
    for (int tm = 0; tm < 2; tm++) {
        #pragma unroll
        for (int h = 0; h < 2; h++) {
            int row = m0 + warpRow * 32 + tm * 16 + 8 * h + qr;
            float dotl = 0.f, dotr = 0.f;
            #pragma unroll
            for (int tn = 0; tn < 8; tn++) {
                float v0 = acc[tm][tn][2 * h + 0];
                float v1 = acc[tm][tn][2 * h + 1];
                int col = warpCol * 64 + tn * 8 + qc * 2;
                dotl = fmaf(v0, __ldg(al + col), fmaf(v1, __ldg(al + col + 1), dotl));
                dotr = fmaf(v0, __ldg(ar_ + col), fmaf(v1, __ldg(ar_ + col + 1), dotr));
                if (row < M)
                    *(__half2*)(fth + (size_t)row * HF + col) = __floats2half2_rn(v0, v1);
            }
            dotl += __shfl_xor_sync(0xffffffffu, dotl, 1);
            dotl += __shfl_xor_sync(0xffffffffu, dotl, 2);
            dotr += __shfl_xor_sync(0xffffffffu, dotr, 1);
            dotr += __shfl_xor_sync(0xffffffffu, dotr, 2);
            if (qc == 0 && row < M) {
                el[row * 2 + warpCol] = dotl;
                er[row * 2 + warpCol] = dotr;
            }
        }
    }
}

// ===========================================================================
// CSR build
// hist: atomicAdd returns each edge's rank within its dst bucket — persist it
// so the scatter pass needs NO atomics.
// ===========================================================================
__global__ void __launch_bounds__(256)
hist_dst(const int4* __restrict__ dst4) {
    int stride = gridDim.x * blockDim.x;
    for (int i = blockIdx.x * blockDim.x + threadIdx.x; i < N_EDGES / 4; i += stride) {
        int4 d = __ldcs(dst4 + i);
        int4 r;
        r.x = atomicAdd(&g_deg[d.x], 1);
        r.y = atomicAdd(&g_deg[d.y], 1);
        r.z = atomicAdd(&g_deg[d.z], 1);
        r.w = atomicAdd(&g_deg[d.w], 1);
        __stcs((int4*)g_rank + i, r);
    }
}

__device__ __forceinline__ int warp_incl_scan(int v, int lane) {
    #pragma unroll
    for (int d = 1; d < 32; d <<= 1) {
        int t = __shfl_up_sync(0xffffffffu, v, d);
        if (lane >= d) v += t;
    }
    return v;
}

// Single-pass scan with decoupled lookback; zeroes g_deg + resets its flags.
__global__ void scan_fused() {
    __shared__ int ws[32];
    __shared__ int sprefix;
    int tid = threadIdx.x;
    int lane = tid & 31, wid = tid >> 5;
    int b = blockIdx.x;
    int i = b * 1024 + tid;
    int v = (i < N_NODES) ? g_deg[i] : 0;
    int incl = warp_incl_scan(v, lane);
    if (lane == 31) ws[wid] = incl;
    __syncthreads();
    if (wid == 0) ws[lane] = warp_incl_scan(ws[lane], lane);
    __syncthreads();
    int local = incl + (wid > 0 ? ws[wid - 1] : 0);
    int btotal = ws[31];

    if (wid == 0) {
        if (lane == 0) {
            g_scanagg[b] = btotal;
            __threadfence();
            atomicExch(&g_scanflag[b], 1);
        }
        int pref = 0;
        for (int p = lane; p < b; p += 32) {
            while (atomicAdd(&g_scanflag[p], 0) == 0) {}
            pref += atomicAdd(&g_scanagg[p], 0);
        }
        #pragma unroll
        for (int d = 16; d; d >>= 1) pref += __shfl_xor_sync(0xffffffffu, pref, d);
        if (lane == 0) {
            sprefix = pref;
            __threadfence();
            int d = atomicAdd(&g_scandone, 1);
            if (d == SCAN_BLOCKS - 1) {
                for (int p = 0; p < SCAN_BLOCKS; p++) g_scanflag[p] = 0;
                g_scandone = 0;
            }
        }
    }
    __syncthreads();
    int ginc = local + sprefix;
    if (i < N_NODES) {
        g_off[i + 1] = ginc;
        g_deg[i] = 0;                              // restore invariant
    }
    if (b == 0 && tid == 0) g_off[0] = 0;
}

// Atomic-free scatter: position = off[dst] + precomputed rank.
__global__ void __launch_bounds__(256)
scatter_edges(const int4* __restrict__ src4, const int4* __restrict__ dst4) {
    int i = blockIdx.x * blockDim.x + threadIdx.x;
    if (i < N_EDGES / 4) {
        int4 s = __ldcs(src4 + i);
        int4 d = __ldcs(dst4 + i);
        int4 r = __ldcs((const int4*)g_rank + i);
        g_ssrc[g_off[d.x] + r.x] = s.x;
        g_ssrc[g_off[d.y] + r.y] = s.y;
        g_ssrc[g_off[d.z] + r.z] = s.z;
        g_ssrc[g_off[d.w] + r.w] = s.w;
    }
}

// ===========================================================================
// warp-per-node softmax + aggregation: 2 edges/iter, half-warp per edge,
// uint4 (8-half) ft loads.
// ===========================================================================
__global__ void gat_agg(float* __restrict__ out) {
    int gtid = blockIdx.x * blockDim.x + threadIdx.x;
    int node = gtid >> 5;
    int lane = gtid & 31;
    if (node >= N_NODES) return;

    const int beg = g_off[node];
    const int end = g_off[node + 1];
    const float er0 = g_er[node * 2 + 0];
    const float er1 = g_er[node * 2 + 1];
    const int half16 = lane >> 4;
    const int l16 = lane & 15;
    const int head = l16 >> 3;

    const uint4* ftp = (const uint4*)g_fth;
    float acc[8];
    #pragma unroll
    for (int j = 0; j < 8; j++) acc[j] = 0.f;
    float s0 = 0.f, s1 = 0.f;

    for (int cb = beg; cb < end; cb += 32) {
        int i = cb + lane;
        float p0 = 0.f, p1 = 0.f;
        int sv = 0;
        if (i < end) {
            sv = __ldcs(g_ssrc + i);
            float2 elv = *(const float2*)(g_el + 2 * sv);
            float e0 = elv.x + er0; e0 = fmaxf(e0, NEG_SLOPE * e0);
            float e1 = elv.y + er1; e1 = fmaxf(e1, NEG_SLOPE * e1);
            p0 = __expf(e0);
            p1 = __expf(e1);
        }
        s0 += p0; s1 += p1;
        int cnt = min(32, end - cb);
        #pragma unroll 2
        for (int e = 0; e < cnt; e += 2) {
            int eA = e + half16;
            bool valid = eA < cnt;
            int esel = valid ? eA : 0;
            int   ss  = __shfl_sync(0xffffffffu, sv, esel);
            float pp0 = __shfl_sync(0xffffffffu, p0, esel);
            float pp1 = __shfl_sync(0xffffffffu, p1, esel);
            float pp = head ? pp1 : pp0;
            if (!valid) pp = 0.f;
            uint4 v = ftp[(size_t)ss * 16 + l16];
            float2 f0 = __half22float2(*(__half2*)&v.x);
            float2 f1 = __half22float2(*(__half2*)&v.y);
            float2 f2 = __half22float2(*(__half2*)&v.z);
            float2 f3 = __half22float2(*(__half2*)&v.w);
            acc[0] = fmaf(pp, f0.x, acc[0]);
            acc[1] = fmaf(pp, f0.y, acc[1]);
            acc[2] = fmaf(pp, f1.x, acc[2]);
            acc[3] = fmaf(pp, f1.y, acc[3]);
            acc[4] = fmaf(pp, f2.x, acc[4]);
            acc[5] = fmaf(pp, f2.y, acc[5]);
            acc[6] = fmaf(pp, f3.x, acc[6]);
            acc[7] = fmaf(pp, f3.y, acc[7]);
        }
    }

    #pragma unroll
    for (int j = 0; j < 8; j++)
        acc[j] += __shfl_xor_sync(0xffffffffu, acc[j], 16);

    #pragma unroll
    for (int d = 16; d; d >>= 1) {
        s0 += __shfl_xor_sync(0xffffffffu, s0, d);
        s1 += __shfl_xor_sync(0xffffffffu, s1, d);
    }
    float inv = 1.f / fmaxf(head ? s1 : s0, 1e-20f);

    if (half16 == 0) {
        float4* op = (float4*)(out + (size_t)node * HF + l16 * 8);
        __stcs(op,     make_float4(acc[0] * inv, acc[1] * inv, acc[2] * inv, acc[3] * inv));
        __stcs(op + 1, make_float4(acc[4] * inv, acc[5] * inv, acc[6] * inv, acc[7] * inv));
    }
}

// ===========================================================================
extern "C" void kernel_launch(void* const* d_in, const int* in_sizes, int n_in,
                              void* d_out, int out_size) {
    const float* feat   = (const float*)d_in[0];
    const int*   src    = (const int*)  d_in[1];
    const int*   dst    = (const int*)  d_in[2];
    const float* W      = (const float*)d_in[3];
    const float* attn_l = (const float*)d_in[4];
    const float* attn_r = (const float*)d_in[5];
    float* out = (float*)d_out;

    __half* fth_p; cudaGetSymbolAddress((void**)&fth_p, g_fth);
    float*  el_p;  cudaGetSymbolAddress((void**)&el_p, g_el);
    float*  er_p;  cudaGetSymbolAddress((void**)&er_p, g_er);

    cudaFuncSetAttribute(gemm_mma, cudaFuncAttributeMaxDynamicSharedMemorySize, SM_TOTAL);

    static cudaStream_t s1 = [] {
        cudaStream_t s; cudaStreamCreateWithFlags(&s, cudaStreamNonBlocking); return s;
    }();
    static cudaEvent_t e0 = [] {
        cudaEvent_t e; cudaEventCreateWithFlags(&e, cudaEventDisableTiming); return e;
    }();
    static cudaEvent_t e1 = [] {
        cudaEvent_t e; cudaEventCreateWithFlags(&e, cudaEventDisableTiming); return e;
    }();

    // Fork: GEMM on s1 (independent of CSR build).
    cudaEventRecord(e0, 0);
    cudaStreamWaitEvent(s1, e0, 0);
    gemm_mma<<<(N_NODES + 127) / 128, 256, SM_TOTAL, s1>>>(feat, W, attn_l, attn_r,
                                                           fth_p, el_p, er_p, N_NODES);
    cudaEventRecord(e1, s1);

    // Main stream: CSR chain (g_deg zero on entry by invariant).
    hist_dst<<<448, 256>>>((const int4*)dst);
    scan_fused<<<SCAN_BLOCKS, 1024>>>();
    scatter_edges<<<(N_EDGES / 4 + 255) / 256, 256>>>((const int4*)src, (const int4*)dst);

    // Join, then aggregate.
    cudaStreamWaitEvent(0, e1, 0);
    gat_agg<<<(N_NODES * 32 + 255) / 256, 256>>>(out);
}

// round 12
// speedup vs baseline: 1.3293x; 1.1078x over previous
#include <cuda_runtime.h>
#include <cuda_bf16.h>
#include <cuda_fp16.h>
#include <math.h>
#include <stdint.h>

#define N_NODES 50000
#define N_EDGES 1600000
#define IN_FEATS 256
#define HF 128           // N_HEADS * OUT_FEATS
#define NEG_SLOPE 0.2f
#define SCAN_BLOCKS 49   // ceil(50000/1024)

// -------- device scratch --------
__device__ __half g_fth[(size_t)N_NODES * HF];  // projected features fp16
__device__ float g_el[N_NODES * 2];
__device__ float g_er[N_NODES * 2];
__device__ int   g_deg[N_NODES];                // zero at every call entry (invariant)
__device__ int   g_off[N_NODES + 1];
__device__ int   g_rank[N_EDGES];               // per-edge rank within dst bucket
__device__ int   g_ssrc[N_EDGES];               // src ids sorted by dst
__device__ int   g_scanflag[64];                // 0 at call entry (invariant)
__device__ int   g_scanagg[64];
__device__ int   g_scandone;                    // 0 at call entry (invariant)

// ===========================================================================
// helpers
// ===========================================================================
__device__ __forceinline__ uint32_t smem_u32(const void* p) {
    uint32_t a;
    asm("{ .reg .u64 t; cvta.to.shared.u64 t, %1; cvt.u32.u64 %0, t; }" : "=r"(a) : "l"(p));
    return a;
}
__device__ __forceinline__ void ldsm4(uint32_t* r, uint32_t addr) {
    asm volatile("ldmatrix.sync.aligned.m8n8.x4.shared.b16 {%0,%1,%2,%3}, [%4];"
                 : "=r"(r[0]), "=r"(r[1]), "=r"(r[2]), "=r"(r[3]) : "r"(addr));
}
__device__ __forceinline__ void mma16816(float* d, const uint32_t* a, const uint32_t* b) {
    asm volatile("mma.sync.aligned.m16n8k16.row.col.f32.bf16.bf16.f32 "
                 "{%0,%1,%2,%3}, {%4,%5,%6,%7}, {%8,%9}, {%0,%1,%2,%3};"
                 : "+f"(d[0]), "+f"(d[1]), "+f"(d[2]), "+f"(d[3])
                 : "r"(a[0]), "r"(a[1]), "r"(a[2]), "r"(a[3]), "r"(b[0]), "r"(b[1]));
}

// smem layout: two 64 KB buffers (double-buffered K chunks)
#define AHI 0
#define ALO 16384
#define BHI 32768
#define BLO 49152
#define BUFSZ 65536
#define SM_TOTAL (2 * BUFSZ)

// load + bf16-split one 64-wide K chunk into a staging buffer
__device__ __forceinline__ void load_chunk(const float* __restrict__ A,
                                           const float* __restrict__ W,
                                           int m0, int M, int tid, int kc,
                                           char* sbuf) {
    #pragma unroll
    for (int i = 0; i < 16; i++) {
        int idx = tid + i * 256;
        int row = idx >> 5, kp = idx & 31;
        int gr = m0 + row;
        float2 a = (gr < M) ? __ldcs((const float2*)(A + (size_t)gr * IN_FEATS + kc + kp * 2))
                            : make_float2(0.f, 0.f);
        __nv_bfloat16 hx = __float2bfloat16(a.x), hy = __float2bfloat16(a.y);
        float lx = a.x - __bfloat162float(hx), ly = a.y - __bfloat162float(hy);
        uint32_t off = row * 128 + ((kp * 4) ^ ((row & 7) << 4));
        *(__nv_bfloat162*)(sbuf + AHI + off) = __halves2bfloat162(hx, hy);
        *(__nv_bfloat162*)(sbuf + ALO + off) =
            __halves2bfloat162(__float2bfloat16(lx), __float2bfloat16(ly));
    }
    #pragma unroll
    for (int i = 0; i < 32; i++) {
        int idx = tid + i * 256;
        int kr = idx >> 7, n = idx & 127;
        float b = __ldg(W + (size_t)(kc + kr) * HF + n);
        __nv_bfloat16 h = __float2bfloat16(b);
        float l = b - __bfloat162float(h);
        uint32_t off = n * 128 + ((kr * 2) ^ ((n & 7) << 4));
        *(__nv_bfloat16*)(sbuf + BHI + off) = h;
        *(__nv_bfloat16*)(sbuf + BLO + off) = __float2bfloat16(l);
    }
}

// ===========================================================================
// Kernel 1: bf16-split mma.sync GEMM (double-buffered) + fused attn logits
// ===========================================================================
__global__ void __launch_bounds__(256)
gemm_mma(const float* __restrict__ A, const float* __restrict__ W,
         const float* __restrict__ al, const float* __restrict__ ar_,
         __half* __restrict__ fth, float* __restrict__ el, float* __restrict__ er,
         int M) {
    extern __shared__ char smem[];
    const uint32_t sb = smem_u32(smem);
    const int tid = threadIdx.x;
    const int wid = tid >> 5;
    const int lane = tid & 31;
    const int warpRow = wid & 3;
    const int warpCol = wid >> 2;
    const int m0 = blockIdx.x * 128;

    float acc[2][8][4];
    #pragma unroll
    for (int a = 0; a < 2; a++)
        #pragma unroll
        for (int b = 0; b < 8; b++)
            #pragma unroll
            for (int c = 0; c < 4; c++) acc[a][b][c] = 0.f;

    load_chunk(A, W, m0, M, tid, 0, smem);
    __syncthreads();

    for (int c = 0; c < 4; c++) {
        const uint32_t sbc = sb + (c & 1) * BUFSZ;
        if (c < 3)
            load_chunk(A, W, m0, M, tid, (c + 1) * 64, smem + ((c + 1) & 1) * BUFSZ);

        #pragma unroll
        for (int ks = 0; ks < 4; ks++) {
            uint32_t ahi[2][4], alo[2][4], bh[8][2], bl[8][2];
            #pragma unroll
            for (int tm = 0; tm < 2; tm++) {
                int row = warpRow * 32 + tm * 16 + (lane & 15);
                int kb = ks * 32 + ((lane >> 4) << 4);
                uint32_t off = row * 128 + (kb ^ ((row & 7) << 4));
                ldsm4(ahi[tm], sbc + AHI + off);
                ldsm4(alo[tm], sbc + ALO + off);
            }
            #pragma unroll
            for (int tp = 0; tp < 4; tp++) {
                int n = warpCol * 64 + tp * 16 + ((lane >> 4) << 3) + (lane & 7);
                int kb = ks * 32 + (((lane >> 3) & 1) << 4);
                uint32_t off = n * 128 + (kb ^ ((n & 7) << 4));
                uint32_t r[4];
                ldsm4(r, sbc + BHI + off);
                bh[tp * 2][0] = r[0]; bh[tp * 2][1] = r[1];
                bh[tp * 2 + 1][0] = r[2]; bh[tp * 2 + 1][1] = r[3];
                ldsm4(r, sbc + BLO + off);
                bl[tp * 2][0] = r[0]; bl[tp * 2][1] = r[1];
                bl[tp * 2 + 1][0] = r[2]; bl[tp * 2 + 1][1] = r[3];
            }
            #pragma unroll
            for (int tm = 0; tm < 2; tm++)
                #pragma unroll
                for (int tn = 0; tn < 8; tn++) {
                    mma16816(acc[tm][tn], ahi[tm], bh[tn]);
                    mma16816(acc[tm][tn], ahi[tm], bl[tn]);
                    mma16816(acc[tm][tn], alo[tm], bh[tn]);
                }
        }
        __syncthreads();
    }

    const int qr = lane >> 2, qc = lane & 3;
    #pragma unroll
    for (int tm = 0; tm < 2; tm++) {
        #pragma unroll
        for (int h = 0; h < 2; h++) {
            int row = m0 + warpRow * 32 + tm * 16 + 8 * h + qr;
            float dotl = 0.f, dotr = 0.f;
            #pragma unroll
            for (int tn = 0; tn < 8; tn++) {
                float v0 = acc[tm][tn][2 * h + 0];
                float v1 = acc[tm][tn][2 * h + 1];
                int col = warpCol * 64 + tn * 8 + qc * 2;
                dotl = fmaf(v0, __ldg(al + col), fmaf(v1, __ldg(al + col + 1), dotl));
                dotr = fmaf(v0, __ldg(ar_ + col), fmaf(v1, __ldg(ar_ + col + 1), dotr));
                if (row < M)
                    *(__half2*)(fth + (size_t)row * HF + col) = __floats2half2_rn(v0, v1);
            }
            dotl += __shfl_xor_sync(0xffffffffu, dotl, 1);
            dotl += __shfl_xor_sync(0xffffffffu, dotl, 2);
            dotr += __shfl_xor_sync(0xffffffffu, dotr, 1);
            dotr += __shfl_xor_sync(0xffffffffu, dotr, 2);
            if (qc == 0 && row < M) {
                el[row * 2 + warpCol] = dotl;
                er[row * 2 + warpCol] = dotr;
            }
        }
    }
}

// ===========================================================================
// CSR build — hist persists the atomicAdd ranks; scatter is atomic-free.
// ===========================================================================
__global__ void __launch_bounds__(256)
hist_dst(const int4* __restrict__ dst4) {
    int i = blockIdx.x * blockDim.x + threadIdx.x;
    if (i < N_EDGES / 4) {
        int4 d = __ldcs(dst4 + i);
        int4 r;
        r.x = atomicAdd(&g_deg[d.x], 1);
        r.y = atomicAdd(&g_deg[d.y], 1);
        r.z = atomicAdd(&g_deg[d.z], 1);
        r.w = atomicAdd(&g_deg[d.w], 1);
        __stcs((int4*)g_rank + i, r);
    }
}

__device__ __forceinline__ int warp_incl_scan(int v, int lane) {
    #pragma unroll
    for (int d = 1; d < 32; d <<= 1) {
        int t = __shfl_up_sync(0xffffffffu, v, d);
        if (lane >= d) v += t;
    }
    return v;
}

// Single-pass scan with decoupled lookback; zeroes g_deg + resets its flags.
__global__ void scan_fused() {
    __shared__ int ws[32];
    __shared__ int sprefix;
    int tid = threadIdx.x;
    int lane = tid & 31, wid = tid >> 5;
    int b = blockIdx.x;
    int i = b * 1024 + tid;
    int v = (i < N_NODES) ? g_deg[i] : 0;
    int incl = warp_incl_scan(v, lane);
    if (lane == 31) ws[wid] = incl;
    __syncthreads();
    if (wid == 0) ws[lane] = warp_incl_scan(ws[lane], lane);
    __syncthreads();
    int local = incl + (wid > 0 ? ws[wid - 1] : 0);
    int btotal = ws[31];

    if (wid == 0) {
        if (lane == 0) {
            g_scanagg[b] = btotal;
            __threadfence();
            atomicExch(&g_scanflag[b], 1);
        }
        int pref = 0;
        for (int p = lane; p < b; p += 32) {
            while (atomicAdd(&g_scanflag[p], 0) == 0) {}
            pref += atomicAdd(&g_scanagg[p], 0);
        }
        #pragma unroll
        for (int d = 16; d; d >>= 1) pref += __shfl_xor_sync(0xffffffffu, pref, d);
        if (lane == 0) {
            sprefix = pref;
            __threadfence();
            int d = atomicAdd(&g_scandone, 1);
            if (d == SCAN_BLOCKS - 1) {
                for (int p = 0; p < SCAN_BLOCKS; p++) g_scanflag[p] = 0;
                g_scandone = 0;
            }
        }
    }
    __syncthreads();
    int ginc = local + sprefix;
    if (i < N_NODES) {
        g_off[i + 1] = ginc;
        g_deg[i] = 0;                              // restore invariant
    }
    if (b == 0 && tid == 0) g_off[0] = 0;
}

// Atomic-free scatter: position = off[dst] + precomputed rank.
__global__ void __launch_bounds__(256)
scatter_edges(const int4* __restrict__ src4, const int4* __restrict__ dst4) {
    int i = blockIdx.x * blockDim.x + threadIdx.x;
    if (i < N_EDGES / 4) {
        int4 s = __ldcs(src4 + i);
        int4 d = __ldcs(dst4 + i);
        int4 r = __ldcs((const int4*)g_rank + i);
        g_ssrc[g_off[d.x] + r.x] = s.x;
        g_ssrc[g_off[d.y] + r.y] = s.y;
        g_ssrc[g_off[d.z] + r.z] = s.z;
        g_ssrc[g_off[d.w] + r.w] = s.w;
    }
}

// ===========================================================================
// warp-per-node softmax + aggregation: half-warp per edge, uint4 ft loads,
// unrolled x4 for deeper MLP.
// ===========================================================================
__global__ void gat_agg(float* __restrict__ out) {
    int gtid = blockIdx.x * blockDim.x + threadIdx.x;
    int node = gtid >> 5;
    int lane = gtid & 31;
    if (node >= N_NODES) return;

    const int beg = g_off[node];
    const int end = g_off[node + 1];
    const float er0 = g_er[node * 2 + 0];
    const float er1 = g_er[node * 2 + 1];
    const int half16 = lane >> 4;
    const int l16 = lane & 15;
    const int head = l16 >> 3;

    const uint4* ftp = (const uint4*)g_fth;
    float acc[8];
    #pragma unroll
    for (int j = 0; j < 8; j++) acc[j] = 0.f;
    float s0 = 0.f, s1 = 0.f;

    for (int cb = beg; cb < end; cb += 32) {
        int i = cb + lane;
        float p0 = 0.f, p1 = 0.f;
        int sv = 0;
        if (i < end) {
            sv = __ldcs(g_ssrc + i);
            float2 elv = *(const float2*)(g_el + 2 * sv);
            float e0 = elv.x + er0; e0 = fmaxf(e0, NEG_SLOPE * e0);
            float e1 = elv.y + er1; e1 = fmaxf(e1, NEG_SLOPE * e1);
            p0 = __expf(e0);
            p1 = __expf(e1);
        }
        s0 += p0; s1 += p1;
        int cnt = min(32, end - cb);
        #pragma unroll 4
        for (int e = 0; e < cnt; e += 2) {
            int eA = e + half16;
            bool valid = eA < cnt;
            int esel = valid ? eA : 0;
            int   ss  = __shfl_sync(0xffffffffu, sv, esel);
            float pp0 = __shfl_sync(0xffffffffu, p0, esel);
            float pp1 = __shfl_sync(0xffffffffu, p1, esel);
            float pp = head ? pp1 : pp0;
            if (!valid) pp = 0.f;
            uint4 v = ftp[(size_t)ss * 16 + l16];
            float2 f0 = __half22float2(*(__half2*)&v.x);
            float2 f1 = __half22float2(*(__half2*)&v.y);
            float2 f2 = __half22float2(*(__half2*)&v.z);
            float2 f3 = __half22float2(*(__half2*)&v.w);
            acc[0] = fmaf(pp, f0.x, acc[0]);
            acc[1] = fmaf(pp, f0.y, acc[1]);
            acc[2] = fmaf(pp, f1.x, acc[2]);
            acc[3] = fmaf(pp, f1.y, acc[3]);
            acc[4] = fmaf(pp, f2.x, acc[4]);
            acc[5] = fmaf(pp, f2.y, acc[5]);
            acc[6] = fmaf(pp, f3.x, acc[6]);
            acc[7] = fmaf(pp, f3.y, acc[7]);
        }
    }

    #pragma unroll
    for (int j = 0; j < 8; j++)
        acc[j] += __shfl_xor_sync(0xffffffffu, acc[j], 16);

    #pragma unroll
    for (int d = 16; d; d >>= 1) {
        s0 += __shfl_xor_sync(0xffffffffu, s0, d);
        s1 += __shfl_xor_sync(0xffffffffu, s1, d);
    }
    float inv = 1.f / fmaxf(head ? s1 : s0, 1e-20f);

    if (half16 == 0) {
        float4* op = (float4*)(out + (size_t)node * HF + l16 * 8);
        __stcs(op,     make_float4(acc[0] * inv, acc[1] * inv, acc[2] * inv, acc[3] * inv));
        __stcs(op + 1, make_float4(acc[4] * inv, acc[5] * inv, acc[6] * inv, acc[7] * inv));
    }
}

// ===========================================================================
extern "C" void kernel_launch(void* const* d_in, const int* in_sizes, int n_in,
                              void* d_out, int out_size) {
    const float* feat   = (const float*)d_in[0];
    const int*   src    = (const int*)  d_in[1];
    const int*   dst    = (const int*)  d_in[2];
    const float* W      = (const float*)d_in[3];
    const float* attn_l = (const float*)d_in[4];
    const float* attn_r = (const float*)d_in[5];
    float* out = (float*)d_out;

    __half* fth_p; cudaGetSymbolAddress((void**)&fth_p, g_fth);
    float*  el_p;  cudaGetSymbolAddress((void**)&el_p, g_el);
    float*  er_p;  cudaGetSymbolAddress((void**)&er_p, g_er);

    cudaFuncSetAttribute(gemm_mma, cudaFuncAttributeMaxDynamicSharedMemorySize, SM_TOTAL);

    static cudaStream_t s1 = [] {
        cudaStream_t s; cudaStreamCreateWithFlags(&s, cudaStreamNonBlocking); return s;
    }();
    static cudaEvent_t e0 = [] {
        cudaEvent_t e; cudaEventCreateWithFlags(&e, cudaEventDisableTiming); return e;
    }();
    static cudaEvent_t e1 = [] {
        cudaEvent_t e; cudaEventCreateWithFlags(&e, cudaEventDisableTiming); return e;
    }();

    // Fork: GEMM on s1 (independent of CSR build).
    cudaEventRecord(e0, 0);
    cudaStreamWaitEvent(s1, e0, 0);
    gemm_mma<<<(N_NODES + 127) / 128, 256, SM_TOTAL, s1>>>(feat, W, attn_l, attn_r,
                                                           fth_p, el_p, er_p, N_NODES);
    cudaEventRecord(e1, s1);

    // Main stream: CSR chain (g_deg zero on entry by invariant).
    hist_dst<<<(N_EDGES / 4 + 255) / 256, 256>>>((const int4*)dst);
    scan_fused<<<SCAN_BLOCKS, 1024>>>();
    scatter_edges<<<(N_EDGES / 4 + 255) / 256, 256>>>((const int4*)src, (const int4*)dst);

    // Join, then aggregate.
    cudaStreamWaitEvent(0, e1, 0);
    gat_agg<<<(N_NODES * 32 + 255) / 256, 256>>>(out);
}